// round 7
// baseline (speedup 1.0000x reference)
#include <cuda_runtime.h>
#include <cuda_bf16.h>
#include <cooperative_groups.h>

namespace cg = cooperative_groups;

#define D    256
#define F    1024
#define NL   4
#define NC   10
#define CS   8
#define TPB  256

// ---- dynamic smem layout (float offsets) ----
#define BUFSZ    16384                 // 64KB per weight buffer
#define OFF_H    (3 * BUFSZ)           // 49152: residual h [256]
#define OFF_Y    (OFF_H + 256)         // LN out [256]
#define OFF_G    (OFF_Y + 256)         // v0 / hidden [1024]
#define OFF_C    (OFF_G + 1024)        // chunk staging [128]
#define OFF_PS   (OFF_C + 128)         // split-K partials [1120]
#define OFF_RED  (OFF_PS + 1120)       // reduce scratch [32]
#define SMEM_FLOATS (OFF_RED + 32)     // 51968 floats = 207,872 B

__device__ __forceinline__ void cpa16(float* dst, const float* src) {
    unsigned sa = (unsigned)__cvta_generic_to_shared(dst);
    asm volatile("cp.async.cg.shared.global [%0], [%1], 16;" :: "r"(sa), "l"(src));
}
#define CPA_COMMIT() asm volatile("cp.async.commit_group;" ::: "memory")
#define CPA_WAIT(n)  asm volatile("cp.async.wait_group %0;" :: "n"(n) : "memory")

__device__ __forceinline__ float2 blockReduceSum2(float a, float b, float2* red2) {
    #pragma unroll
    for (int o = 16; o > 0; o >>= 1) {
        a += __shfl_xor_sync(0xffffffffu, a, o);
        b += __shfl_xor_sync(0xffffffffu, b, o);
    }
    int wid = threadIdx.x >> 5;
    if ((threadIdx.x & 31) == 0) red2[wid] = make_float2(a, b);
    __syncthreads();
    if (threadIdx.x < 8) {
        float2 t = red2[threadIdx.x];
        #pragma unroll
        for (int o = 4; o > 0; o >>= 1) {
            t.x += __shfl_xor_sync(0xffu, t.x, o);
            t.y += __shfl_xor_sync(0xffu, t.y, o);
        }
        if (threadIdx.x == 0) red2[0] = t;
    }
    __syncthreads();
    float2 r = red2[0];
    __syncthreads();
    return r;
}

__device__ __forceinline__ float gelu_tanh(float x) {
    const float c = 0.7978845608028654f;
    float u = c * (x + 0.044715f * x * x * x);
    return 0.5f * x * (1.0f + tanhf(u));
}

__global__ void __launch_bounds__(TPB, 1) __cluster_dims__(CS, 1, 1)
performer_cls_kernel(const int*   __restrict__ xx,
                     const float* __restrict__ emb_tok,
                     const float* __restrict__ emb_pos,
                     const float* __restrict__ ln1_s,
                     const float* __restrict__ ln1_b,
                     const float* __restrict__ wv,
                     const float* __restrict__ wo,
                     const float* __restrict__ bo,
                     const float* __restrict__ ln2_s,
                     const float* __restrict__ ln2_b,
                     const float* __restrict__ w1,
                     const float* __restrict__ b1,
                     const float* __restrict__ w2,
                     const float* __restrict__ b2,
                     const float* __restrict__ wcls,
                     const float* __restrict__ bcls,
                     float* __restrict__ out,
                     int N)
{
    extern __shared__ float sm[];
    float* sh_h = sm + OFF_H;
    float* sh_y = sm + OFF_Y;
    float* sh_g = sm + OFF_G;
    float* sh_c = sm + OFF_C;
    float* ps   = sm + OFF_PS;
    float2* red2 = (float2*)(sm + OFF_RED);

    cg::cluster_group cluster = cg::this_cluster();
    const int tid = threadIdx.x;
    const int r   = (int)cluster.block_rank();
    const int b   = blockIdx.x >> 3;

    const int c4  = tid & 7;            // A/C: 4 cols each over 32-col tile
    const int ks  = tid >> 3;           // A/C: 32 K-slices
    const int c4b = tid & 31;           // B: 4 cols each over 128-col tile
    const int ksb = tid >> 5;           // B: 8 K-slices
    const int p_dst  = tid >> 5;
    const int p_lane = tid & 31;
    const int j0  = r * 32;
    const int j0b = r * 128;

    // ---- cp.async issue helpers ----
    auto issueA = [&](int l, float* dstb) {           // wv slice -> lo, wo slice -> hi
        const float* Wv = wv + (size_t)l * D * D;
        const float* Wo = wo + (size_t)l * D * D;
        #pragma unroll
        for (int i = 0; i < 8; ++i) {
            int t = tid + i * TPB;                     // 0..2047
            int row = t >> 3, c = t & 7;
            cpa16(dstb + t * 4,        Wv + (size_t)row * D + j0 + c * 4);
            cpa16(dstb + 8192 + t * 4, Wo + (size_t)row * D + j0 + c * 4);
        }
    };
    auto issueB = [&](int l, int h, float* dstb) {    // w1 K-half
        const float* W = w1 + (size_t)l * D * F;
        #pragma unroll
        for (int i = 0; i < 16; ++i) {
            int t = tid + i * TPB;                     // 0..4095
            int row = t >> 5, c = t & 31;
            cpa16(dstb + t * 4, W + (size_t)(h * 128 + row) * F + j0b + c * 4);
        }
    };
    auto issueC = [&](int l, int h, float* dstb) {    // w2 K-half
        const float* W = w2 + (size_t)l * F * D;
        #pragma unroll
        for (int i = 0; i < 16; ++i) {
            int t = tid + i * TPB;                     // 0..4095
            int row = t >> 3, c = t & 7;
            cpa16(dstb + t * 4, W + (size_t)(h * 512 + row) * D + j0 + c * 4);
        }
    };

    // ---- init h0 locally; prologue prefetch of layer-0 A weights ----
    {
        const int tok = xx[b * N];
        sh_h[tid] = emb_tok[tok * D + tid] + emb_pos[tid];
    }
    issueA(0, sm);            // into bufs[0]
    CPA_COMMIT();

    int a = 0;                // A-buffer index, rotates (a+2)%3 per layer
    for (int l = 0; l < NL; ++l) {
        float* bufA = sm + a * BUFSZ;
        float* b1p  = sm + ((a + 1) % 3) * BUFSZ;
        float* b2p  = sm + ((a + 2) % 3) * BUFSZ;

        // ======== stage A1: v0 = LN1(h) @ wv ========
        {
            issueB(l, 0, b1p); CPA_COMMIT();
            CPA_WAIT(1); __syncthreads();             // A-pair ready

            float v = sh_h[tid];
            float2 ss = blockReduceSum2(v, v * v, red2);
            float mu  = ss.x * (1.0f / D);
            float var = ss.y * (1.0f / D) - mu * mu;
            float inv = rsqrtf(var + 1e-5f);
            sh_y[tid] = (v - mu) * inv * ln1_s[l * D + tid] + ln1_b[l * D + tid];
            __syncthreads();

            const float4* wb = (const float4*)bufA;
            float4 a4 = make_float4(0.f, 0.f, 0.f, 0.f);
            #pragma unroll
            for (int i = 0; i < 8; ++i) {
                int k = ks * 8 + i;
                float4 w = wb[k * 8 + c4];
                float yk = sh_y[k];
                a4.x = fmaf(yk, w.x, a4.x); a4.y = fmaf(yk, w.y, a4.y);
                a4.z = fmaf(yk, w.z, a4.z); a4.w = fmaf(yk, w.w, a4.w);
            }
            ps[(c4 * 4 + 0) * 33 + ks] = a4.x;
            ps[(c4 * 4 + 1) * 33 + ks] = a4.y;
            ps[(c4 * 4 + 2) * 33 + ks] = a4.z;
            ps[(c4 * 4 + 3) * 33 + ks] = a4.w;
            __syncthreads();
            if (tid < 32) {
                float acc = 0.0f;
                #pragma unroll
                for (int s = 0; s < 32; ++s) acc += ps[tid * 33 + s];
                sh_c[tid] = acc;
            }
            __syncthreads();
            float* dst = cluster.map_shared_rank(sh_g, p_dst);
            dst[j0 + p_lane] = sh_c[p_lane];
        }
        cluster.sync();

        // ======== stage A2: h += v0 @ wo + bo ========
        {
            issueB(l, 1, b2p); CPA_COMMIT();

            const float4* wb = (const float4*)(bufA + 8192);
            float4 a4 = make_float4(0.f, 0.f, 0.f, 0.f);
            #pragma unroll
            for (int i = 0; i < 8; ++i) {
                int k = ks * 8 + i;
                float4 w = wb[k * 8 + c4];
                float yk = sh_g[k];
                a4.x = fmaf(yk, w.x, a4.x); a4.y = fmaf(yk, w.y, a4.y);
                a4.z = fmaf(yk, w.z, a4.z); a4.w = fmaf(yk, w.w, a4.w);
            }
            ps[(c4 * 4 + 0) * 33 + ks] = a4.x;
            ps[(c4 * 4 + 1) * 33 + ks] = a4.y;
            ps[(c4 * 4 + 2) * 33 + ks] = a4.z;
            ps[(c4 * 4 + 3) * 33 + ks] = a4.w;
            __syncthreads();
            if (tid < 32) {
                float acc = bo[l * D + j0 + tid];
                #pragma unroll
                for (int s = 0; s < 32; ++s) acc += ps[tid * 33 + s];
                sh_c[tid] = sh_h[j0 + tid] + acc;
            }
            __syncthreads();
            float* dst = cluster.map_shared_rank(sh_h, p_dst);
            dst[j0 + p_lane] = sh_c[p_lane];
        }
        cluster.sync();

        // ======== stage B: hidden = gelu(LN2(h) @ w1 + b1) ========
        {
            issueC(l, 0, bufA); CPA_COMMIT();

            float v = sh_h[tid];
            float2 ss = blockReduceSum2(v, v * v, red2);
            float mu  = ss.x * (1.0f / D);
            float var = ss.y * (1.0f / D) - mu * mu;
            float inv = rsqrtf(var + 1e-5f);
            sh_y[tid] = (v - mu) * inv * ln2_s[l * D + tid] + ln2_b[l * D + tid];

            CPA_WAIT(2); __syncthreads();             // Bh1 ready (also LN barrier)

            const float4* wh1 = (const float4*)b1p;
            float4 a4 = make_float4(0.f, 0.f, 0.f, 0.f);
            #pragma unroll
            for (int i = 0; i < 16; ++i) {
                int kl = ksb * 16 + i;
                float4 w = wh1[kl * 32 + c4b];
                float yk = sh_y[kl];
                a4.x = fmaf(yk, w.x, a4.x); a4.y = fmaf(yk, w.y, a4.y);
                a4.z = fmaf(yk, w.z, a4.z); a4.w = fmaf(yk, w.w, a4.w);
            }
            __syncthreads();                          // all done reading b1p
            issueC(l, 1, b1p); CPA_COMMIT();
            CPA_WAIT(2); __syncthreads();             // Bh2 ready

            const float4* wh2 = (const float4*)b2p;
            #pragma unroll
            for (int i = 0; i < 16; ++i) {
                int kl = ksb * 16 + i;
                float4 w = wh2[kl * 32 + c4b];
                float yk = sh_y[128 + kl];
                a4.x = fmaf(yk, w.x, a4.x); a4.y = fmaf(yk, w.y, a4.y);
                a4.z = fmaf(yk, w.z, a4.z); a4.w = fmaf(yk, w.w, a4.w);
            }
            ((float4*)ps)[ksb * 33 + c4b] = a4;
            __syncthreads();
            if (tid < 128) {
                float acc = b1[l * F + j0b + tid];
                #pragma unroll
                for (int s = 0; s < 8; ++s) acc += ps[s * 132 + tid];
                sh_c[tid] = gelu_tanh(acc);
            }
            __syncthreads();
            float* dst = cluster.map_shared_rank(sh_g, p_dst);
            #pragma unroll
            for (int e = 0; e < 4; ++e)
                dst[j0b + p_lane + e * 32] = sh_c[p_lane + e * 32];
        }
        cluster.sync();

        // ======== stage C: h += hidden @ w2 + b2 ========
        {
            issueA((l + 1) % NL, b2p); CPA_COMMIT();
            CPA_WAIT(2); __syncthreads();             // Ch1 ready

            const float4* wh1 = (const float4*)bufA;
            float4 a4 = make_float4(0.f, 0.f, 0.f, 0.f);
            #pragma unroll
            for (int i = 0; i < 16; ++i) {
                int kl = ks * 16 + i;
                float4 w = wh1[kl * 8 + c4];
                float yk = sh_g[kl];
                a4.x = fmaf(yk, w.x, a4.x); a4.y = fmaf(yk, w.y, a4.y);
                a4.z = fmaf(yk, w.z, a4.z); a4.w = fmaf(yk, w.w, a4.w);
            }
            CPA_WAIT(1); __syncthreads();             // Ch2 ready

            const float4* wh2 = (const float4*)b1p;
            #pragma unroll
            for (int i = 0; i < 16; ++i) {
                int kl = ks * 16 + i;
                float4 w = wh2[kl * 8 + c4];
                float yk = sh_g[512 + kl];
                a4.x = fmaf(yk, w.x, a4.x); a4.y = fmaf(yk, w.y, a4.y);
                a4.z = fmaf(yk, w.z, a4.z); a4.w = fmaf(yk, w.w, a4.w);
            }
            ps[(c4 * 4 + 0) * 33 + ks] = a4.x;
            ps[(c4 * 4 + 1) * 33 + ks] = a4.y;
            ps[(c4 * 4 + 2) * 33 + ks] = a4.z;
            ps[(c4 * 4 + 3) * 33 + ks] = a4.w;
            __syncthreads();
            if (tid < 32) {
                float acc = b2[l * D + j0 + tid];
                #pragma unroll
                for (int s = 0; s < 32; ++s) acc += ps[tid * 33 + s];
                sh_c[tid] = sh_h[j0 + tid] + acc;
            }
            __syncthreads();
            float* dst = cluster.map_shared_rank(sh_h, p_dst);
            dst[j0 + p_lane] = sh_c[p_lane];
        }
        cluster.sync();

        a = (a + 2) % 3;
    }

    // ======== classifier (rank 0) ========
    if (r == 0) {
        if (tid < 160) {
            const int c = tid >> 4;
            const int s = tid & 15;
            float acc = 0.0f;
            #pragma unroll
            for (int i = 0; i < 16; ++i) {
                int k = s * 16 + i;
                acc = fmaf(sh_h[k], wcls[k * NC + c], acc);
            }
            ps[c * 17 + s] = acc;
        }
        __syncthreads();
        if (tid < NC) {
            float acc = bcls[tid];
            #pragma unroll
            for (int s = 0; s < 16; ++s) acc += ps[tid * 17 + s];
            out[b * NC + tid] = acc;
        }
    }
}

extern "C" void kernel_launch(void* const* d_in, const int* in_sizes, int n_in,
                              void* d_out, int out_size)
{
    const int*   xx      = (const int*)  d_in[0];
    const float* emb_tok = (const float*)d_in[1];
    const float* emb_pos = (const float*)d_in[2];
    const float* ln1_s   = (const float*)d_in[4];
    const float* ln1_b   = (const float*)d_in[5];
    const float* wv      = (const float*)d_in[8];
    const float* wo      = (const float*)d_in[9];
    const float* bo      = (const float*)d_in[10];
    const float* ln2_s   = (const float*)d_in[11];
    const float* ln2_b   = (const float*)d_in[12];
    const float* w1      = (const float*)d_in[13];
    const float* b1      = (const float*)d_in[14];
    const float* w2      = (const float*)d_in[15];
    const float* b2      = (const float*)d_in[16];
    const float* wcls    = (const float*)d_in[17];
    const float* bcls    = (const float*)d_in[18];
    float* out = (float*)d_out;

    const int B = out_size / NC;      // 16
    const int N = in_sizes[0] / B;    // 4096
    const size_t smem_bytes = (size_t)SMEM_FLOATS * sizeof(float);

    cudaFuncSetAttribute(performer_cls_kernel,
                         cudaFuncAttributeMaxDynamicSharedMemorySize,
                         (int)smem_bytes);

    performer_cls_kernel<<<B * CS, TPB, smem_bytes>>>(
        xx, emb_tok, emb_pos, ln1_s, ln1_b, wv, wo, bo, ln2_s, ln2_b,
        w1, b1, w2, b2, wcls, bcls, out, N);
}